// round 5
// baseline (speedup 1.0000x reference)
#include <cuda_runtime.h>
#include <cuda_bf16.h>
#include <cstdint>

// Problem constants
#define NB   32
#define DIM  256
#define HWD  1024
#define NV   (NB*HWD)        // 32768 vectors
#define NK   1024            // codes
#define NELEM (NV*DIM)

// Scratch
__device__ float         g_flat[NV * DIM];       // z transposed [vec, d] fp32
__device__ __nv_bfloat16 g_flat_bf16[NV * DIM];  // bf16 copy for MMA A tiles
__device__ uint32_t      g_emb_bf16[NK * 128];   // bf16x2 codebook for B tiles
__device__ float         g_ee[NK];               // ||e_k||^2
__device__ double        g_loss_sum;

// ===========================================================================
// cp.async helpers (sm_80 PTX, fine for compute_103 target)
// ===========================================================================
__device__ __forceinline__ uint32_t smem_u32(const void* p) {
    uint32_t a;
    asm("{ .reg .u64 t; cvta.to.shared.u64 t, %1; cvt.u32.u64 %0, t; }" : "=r"(a) : "l"(p));
    return a;
}
#define CP_ASYNC16(d, s) asm volatile("cp.async.cg.shared.global [%0], [%1], 16;" :: "r"(d), "l"(s))
#define CP_COMMIT()      asm volatile("cp.async.commit_group;" ::: "memory")
#define CP_WAIT0()       asm volatile("cp.async.wait_group 0;" ::: "memory")

// ===========================================================================
// Transpose NCHW -> [vec, d]; also emit bf16 copy.
__global__ void vq_transpose_kernel(const float* __restrict__ z) {
    __shared__ float t[32][33];
    const int p0 = blockIdx.x * 32, d0 = blockIdx.y * 32, b = blockIdx.z;
    const int x = threadIdx.x, y = threadIdx.y;
#pragma unroll
    for (int j = 0; j < 32; j += 8)
        t[y + j][x] = z[b * (DIM * HWD) + (d0 + y + j) * HWD + p0 + x];
    __syncthreads();
#pragma unroll
    for (int j = 0; j < 32; j += 8) {
        const float v = t[x][y + j];
        const size_t o = (size_t)(b * HWD + p0 + y + j) * DIM + d0 + x;
        g_flat[o] = v;
        g_flat_bf16[o] = __float2bfloat16(v);
    }
}

// Codebook norms + bf16 codebook + loss zero. One warp per code.
__global__ void vq_enorm_kernel(const float* __restrict__ emb) {
    const int k = blockIdx.x, lane = threadIdx.x;
    if (k == 0 && lane == 0) g_loss_sum = 0.0;
    const float4* r4 = reinterpret_cast<const float4*>(emb + k * DIM);
    float4 a = r4[lane], b = r4[lane + 32];
    // bf16 copy
    uint32_t* dst = g_emb_bf16 + k * 128;
    __nv_bfloat162 p;
    p = __float22bfloat162_rn(make_float2(a.x, a.y)); dst[lane*2]      = *reinterpret_cast<uint32_t*>(&p);
    p = __float22bfloat162_rn(make_float2(a.z, a.w)); dst[lane*2+1]    = *reinterpret_cast<uint32_t*>(&p);
    p = __float22bfloat162_rn(make_float2(b.x, b.y)); dst[64+lane*2]   = *reinterpret_cast<uint32_t*>(&p);
    p = __float22bfloat162_rn(make_float2(b.z, b.w)); dst[64+lane*2+1] = *reinterpret_cast<uint32_t*>(&p);
    float s = a.x*a.x + a.y*a.y + a.z*a.z + a.w*a.w
            + b.x*b.x + b.y*b.y + b.z*b.z + b.w*b.w;
#pragma unroll
    for (int off = 16; off; off >>= 1) s += __shfl_xor_sync(0xffffffffu, s, off);
    if (lane == 0) g_ee[k] = s;
}

// ===========================================================================
// Mega kernel: HMMA GEMM + fused approx-d2 argmin filter + exact rescore +
// gather/straight-through/loss.  1 CTA = 128 rows, 256 threads.
// ===========================================================================
#define SM_PITCH 528                      // bytes per padded bf16 row
#define TILE_BYTES (128 * SM_PITCH)       // 67584
#define MEGA_SMEM (3 * TILE_BYTES)        // A + 2x B
#define CAND_CAP 16

__device__ __forceinline__ void mma_bf16(float& c0, float& c1, float& c2, float& c3,
                                         uint32_t a0, uint32_t a1, uint32_t a2, uint32_t a3,
                                         uint32_t b0, uint32_t b1) {
    asm volatile(
        "mma.sync.aligned.m16n8k16.row.col.f32.bf16.bf16.f32 "
        "{%0,%1,%2,%3}, {%4,%5,%6,%7}, {%8,%9}, {%0,%1,%2,%3};"
        : "+f"(c0), "+f"(c1), "+f"(c2), "+f"(c3)
        : "r"(a0), "r"(a1), "r"(a2), "r"(a3), "r"(b0), "r"(b1));
}

// copy a [128 x 512B] bf16 tile into padded smem via cp.async
__device__ __forceinline__ void fill_async(uint32_t tile_s, const char* __restrict__ src, int tid) {
#pragma unroll
    for (int i = tid; i < 4096; i += 256) {
        const int row = i >> 5, ch = (i & 31) << 4;
        CP_ASYNC16(tile_s + row * SM_PITCH + ch, src + row * 512 + ch);
    }
}

__device__ __forceinline__ float warp_dot256(const float* __restrict__ x,
                                             const float* __restrict__ e, int lane) {
    const float4* x4 = reinterpret_cast<const float4*>(x);
    const float4* e4 = reinterpret_cast<const float4*>(e);
    float4 a = x4[lane], b = e4[lane], a2 = x4[lane + 32], b2 = e4[lane + 32];
    float s = a.x * b.x;
    s = fmaf(a.y, b.y, s);  s = fmaf(a.z, b.z, s);  s = fmaf(a.w, b.w, s);
    s = fmaf(a2.x, b2.x, s); s = fmaf(a2.y, b2.y, s);
    s = fmaf(a2.z, b2.z, s); s = fmaf(a2.w, b2.w, s);
#pragma unroll
    for (int off = 16; off; off >>= 1) s += __shfl_xor_sync(0xffffffffu, s, off);
    return s;
}

__global__ __launch_bounds__(256, 1) void vq_mega_kernel(const float* __restrict__ emb,
                                                         float* __restrict__ out) {
    extern __shared__ char sm[];
    char* sA  = sm;
    char* sB0 = sm + TILE_BYTES;
    char* sB1 = sm + 2 * TILE_BYTES;
    const uint32_t aA = smem_u32(sA), aB0 = smem_u32(sB0), aB1 = smem_u32(sB1);

    __shared__ float    s_xx[128];
    __shared__ float    s_margin[128];
    __shared__ unsigned s_min[128];
    __shared__ int      s_cnt[128];
    __shared__ int      s_cand[128][CAND_CAP];
    __shared__ int      s_idx[128];
    __shared__ float    s_ee[NK];
    __shared__ float    wsum[8];

    const int tid  = threadIdx.x;
    const int lane = tid & 31;
    const int wid  = tid >> 5;
    const int warp_m = wid & 1;
    const int warp_n = wid >> 1;
    const int g   = lane >> 2;
    const int tig = lane & 3;
    const int m0  = blockIdx.x * 128;

    // launch async fills for A and B0
    fill_async(aA,  (const char*)g_flat_bf16 + (size_t)m0 * 512, tid);
    fill_async(aB0, (const char*)g_emb_bf16, tid);
    CP_COMMIT();

    // xx for this CTA's rows (bit-identical order to proven row_norm2)
#pragma unroll
    for (int j = 0; j < 16; j++) {
        const int r = wid * 16 + j;
        const float* row = g_flat + (size_t)(m0 + r) * DIM;
        const float4* r4 = reinterpret_cast<const float4*>(row);
        float4 a = r4[lane], b = r4[lane + 32];
        float s = a.x*a.x + a.y*a.y + a.z*a.z + a.w*a.w
                + b.x*b.x + b.y*b.y + b.z*b.z + b.w*b.w;
#pragma unroll
        for (int off = 16; off; off >>= 1) s += __shfl_xor_sync(0xffffffffu, s, off);
        if (lane == 0) {
            s_xx[r] = s;
            // rigorous margin: 12*2^-9 * ||x|| * ||e||max + slack (||e|| < 1/64)
            s_margin[r] = sqrtf(s) * 0.015625f * (12.0f / 512.0f) + 3e-4f;
            s_min[r] = 0x7f7fffffu;   // +FLT_MAX bits
            s_cnt[r] = 0;
        }
    }
    for (int i = tid; i < NK; i += 256) s_ee[i] = g_ee[i];

    CP_WAIT0();
    __syncthreads();

    // per-warp smem byte bases (R4-proven fragment addressing)
    int aBase[4], bBase[4];
#pragma unroll
    for (int mf = 0; mf < 4; mf++) aBase[mf] = (warp_m * 64 + mf * 16 + g) * SM_PITCH;
#pragma unroll
    for (int nf = 0; nf < 4; nf++) bBase[nf] = (warp_n * 32 + nf * 8 + g) * SM_PITCH;
    const int kb0 = tig * 4;

    for (int t = 0; t < 8; t++) {
        char* sB = (t & 1) ? sB1 : sB0;
        if (t < 7) {
            fill_async(((t + 1) & 1) ? aB1 : aB0,
                       (const char*)g_emb_bf16 + (size_t)(t + 1) * 65536, tid);
            CP_COMMIT();
        }

        float acc[4][4][4];
#pragma unroll
        for (int mf = 0; mf < 4; mf++)
#pragma unroll
            for (int nf = 0; nf < 4; nf++)
#pragma unroll
                for (int c = 0; c < 4; c++) acc[mf][nf][c] = 0.f;

#pragma unroll
        for (int ks = 0; ks < 16; ks++) {
            const int kb = ks * 32 + kb0;
            uint32_t a[4][4], b[4][2];
#pragma unroll
            for (int mf = 0; mf < 4; mf++) {
                const char* p0 = sA + aBase[mf] + kb;
                a[mf][0] = *reinterpret_cast<const uint32_t*>(p0);
                a[mf][1] = *reinterpret_cast<const uint32_t*>(p0 + 8 * SM_PITCH);
                a[mf][2] = *reinterpret_cast<const uint32_t*>(p0 + 16);
                a[mf][3] = *reinterpret_cast<const uint32_t*>(p0 + 8 * SM_PITCH + 16);
            }
#pragma unroll
            for (int nf = 0; nf < 4; nf++) {
                const char* p0 = sB + bBase[nf] + kb;
                b[nf][0] = *reinterpret_cast<const uint32_t*>(p0);
                b[nf][1] = *reinterpret_cast<const uint32_t*>(p0 + 16);
            }
#pragma unroll
            for (int mf = 0; mf < 4; mf++)
#pragma unroll
                for (int nf = 0; nf < 4; nf++)
                    mma_bf16(acc[mf][nf][0], acc[mf][nf][1], acc[mf][nf][2], acc[mf][nf][3],
                             a[mf][0], a[mf][1], a[mf][2], a[mf][3],
                             b[nf][0], b[nf][1]);
        }

        // ---- fused filter epilogue: approx d2, running min, candidates ----
#pragma unroll
        for (int mf = 0; mf < 4; mf++) {
            const int r1 = warp_m * 64 + mf * 16 + g, r2 = r1 + 8;
            const float xx1 = s_xx[r1], xx2 = s_xx[r2];
#pragma unroll
            for (int nf = 0; nf < 4; nf++) {
                const int c0 = t * 128 + warp_n * 32 + nf * 8 + tig * 2;
                const float e0 = s_ee[c0], e1 = s_ee[c0 + 1];
                acc[mf][nf][0] = __fadd_rn(__fmaf_rn(-2.f, acc[mf][nf][0], xx1), e0);
                acc[mf][nf][1] = __fadd_rn(__fmaf_rn(-2.f, acc[mf][nf][1], xx1), e1);
                acc[mf][nf][2] = __fadd_rn(__fmaf_rn(-2.f, acc[mf][nf][2], xx2), e0);
                acc[mf][nf][3] = __fadd_rn(__fmaf_rn(-2.f, acc[mf][nf][3], xx2), e1);
                atomicMin(&s_min[r1], __float_as_uint(acc[mf][nf][0]));
                atomicMin(&s_min[r1], __float_as_uint(acc[mf][nf][1]));
                atomicMin(&s_min[r2], __float_as_uint(acc[mf][nf][2]));
                atomicMin(&s_min[r2], __float_as_uint(acc[mf][nf][3]));
            }
        }
        __syncthreads();
#pragma unroll
        for (int mf = 0; mf < 4; mf++) {
            const int r1 = warp_m * 64 + mf * 16 + g, r2 = r1 + 8;
            const float th1 = __uint_as_float(s_min[r1]) + s_margin[r1];
            const float th2 = __uint_as_float(s_min[r2]) + s_margin[r2];
#pragma unroll
            for (int nf = 0; nf < 4; nf++) {
                const int c0 = t * 128 + warp_n * 32 + nf * 8 + tig * 2;
                if (acc[mf][nf][0] <= th1) { int p = atomicAdd(&s_cnt[r1], 1); if (p < CAND_CAP) s_cand[r1][p] = c0; }
                if (acc[mf][nf][1] <= th1) { int p = atomicAdd(&s_cnt[r1], 1); if (p < CAND_CAP) s_cand[r1][p] = c0 + 1; }
                if (acc[mf][nf][2] <= th2) { int p = atomicAdd(&s_cnt[r2], 1); if (p < CAND_CAP) s_cand[r2][p] = c0; }
                if (acc[mf][nf][3] <= th2) { int p = atomicAdd(&s_cnt[r2], 1); if (p < CAND_CAP) s_cand[r2][p] = c0 + 1; }
            }
        }

        if (t < 7) CP_WAIT0();
        __syncthreads();
    }

    // ---- exact fp32 rescore (reference rounding + lowest-index ties) ----
#pragma unroll 1
    for (int j = 0; j < 16; j++) {
        const int r = wid * 16 + j;
        const float xx = s_xx[r];
        const float* xrow = g_flat + (size_t)(m0 + r) * DIM;
        const int cnt = s_cnt[r];
        unsigned long long best = ~0ull;
        if (cnt <= CAND_CAP) {
#pragma unroll 1
            for (int k = 0; k < cnt; k++) {
                const int code = s_cand[r][k];
                const float dot = warp_dot256(xrow, emb + (size_t)code * DIM, lane);
                const float d2  = __fadd_rn(__fmaf_rn(-2.f, dot, xx), s_ee[code]);
                const unsigned long long key =
                    ((unsigned long long)__float_as_uint(d2) << 32) | (unsigned)code;
                best = (key < best) ? key : best;
            }
        } else {  // deterministic fallback: full rescan
#pragma unroll 1
            for (int code = 0; code < NK; code++) {
                const float dot = warp_dot256(xrow, emb + (size_t)code * DIM, lane);
                const float d2  = __fadd_rn(__fmaf_rn(-2.f, dot, xx), s_ee[code]);
                const unsigned long long key =
                    ((unsigned long long)__float_as_uint(d2) << 32) | (unsigned)code;
                best = (key < best) ? key : best;
            }
        }
        if (lane == 0) s_idx[r] = (int)(best & 0xffffffffu);
    }
    __syncthreads();

    // ---- gather + straight-through + loss (R2-proven semantics) ----
    float (*tbuf)[33] = reinterpret_cast<float(*)[33]>(sA);  // overlay on A tile
    const int b_img = m0 >> 10;
    const int hw0   = m0 & (HWD - 1);
    const int dx = tid & 31;
    const int wy = tid >> 5;
    float lsum = 0.f;

    for (int dt = 0; dt < DIM; dt += 32) {
        for (int vt = 0; vt < 128; vt += 32) {
#pragma unroll
            for (int vv = 0; vv < 32; vv += 8) {
                const int v    = vt + vv + wy;
                const int code = s_idx[v];
                const float e  = emb[code * DIM + dt + dx];
                const float x  = g_flat[(size_t)(m0 + v) * DIM + dt + dx];
                const float df = __fadd_rn(e, -x);
                lsum += df * df;
                tbuf[vv + wy][dx] = __fadd_rn(x, df);
            }
            __syncthreads();
#pragma unroll
            for (int dd = 0; dd < 32; dd += 8) {
                const int d = dt + dd + wy;
                out[(b_img * DIM + d) * HWD + hw0 + vt + dx] = tbuf[dx][dd + wy];
            }
            __syncthreads();
        }
    }

#pragma unroll
    for (int off = 16; off; off >>= 1) lsum += __shfl_xor_sync(0xffffffffu, lsum, off);
    if ((tid & 31) == 0) wsum[tid >> 5] = lsum;
    __syncthreads();
    if (tid == 0) {
        float tot = 0.f;
#pragma unroll
        for (int w = 0; w < 8; w++) tot += wsum[w];
        atomicAdd(&g_loss_sum, (double)tot);
    }
}

// ===========================================================================
__global__ void vq_finalize_kernel(float* __restrict__ out) {
    const double mean = g_loss_sum * (1.0 / (double)NELEM);
    const float cb = (float)mean;
    out[NELEM + 0] = cb + 0.25f * cb;
    out[NELEM + 1] = cb;
    out[NELEM + 2] = cb;
}

// ===========================================================================
extern "C" void kernel_launch(void* const* d_in, const int* in_sizes, int n_in,
                              void* d_out, int out_size) {
    const float* z   = (const float*)d_in[0];
    const float* emb = (const float*)d_in[1];
    if (n_in >= 2 && in_sizes[0] == NK * DIM && in_sizes[1] == NELEM) {
        const float* t = z; z = emb; emb = t;
    }
    float* out = (float*)d_out;

    cudaFuncSetAttribute(vq_mega_kernel,
                         cudaFuncAttributeMaxDynamicSharedMemorySize, MEGA_SMEM);

    vq_transpose_kernel<<<dim3(HWD / 32, DIM / 32, NB), dim3(32, 8)>>>(z);
    vq_enorm_kernel<<<NK, 32>>>(emb);
    vq_mega_kernel<<<NV / 128, 256, MEGA_SMEM>>>(emb, out);
    vq_finalize_kernel<<<1, 1>>>(out);
}

// round 6
// speedup vs baseline: 6.3463x; 6.3463x over previous
#include <cuda_runtime.h>
#include <cuda_bf16.h>
#include <cstdint>

// Problem constants
#define NB   32
#define DIM  256
#define HWD  1024
#define NV   (NB*HWD)        // 32768 vectors
#define NK   1024            // codes
#define NELEM (NV*DIM)

// Scratch
__device__ float                   g_flat[NV * DIM];       // z transposed [vec, d] fp32
__device__ __align__(16) __nv_bfloat16 g_flat_bf16[NV * DIM];  // bf16 copy (A tiles)
__device__ __align__(16) uint32_t  g_emb_bf16[NK * 128];   // bf16x2 codebook (B tiles)
__device__ float                   g_ee[NK];               // ||e_k||^2
__device__ uint32_t                g_dots_u32[NV * (NK/2)];// approx dots, bf16x2 packed
__device__ int                     g_win[NV];              // winning code per row
__device__ double                  g_loss_sum;

// ===========================================================================
__device__ __forceinline__ uint32_t smem_u32(const void* p) {
    uint32_t a;
    asm("{ .reg .u64 t; cvta.to.shared.u64 t, %1; cvt.u32.u64 %0, t; }" : "=r"(a) : "l"(p));
    return a;
}
#define CP_ASYNC16(d, s) asm volatile("cp.async.cg.shared.global [%0], [%1], 16;" :: "r"(d), "l"(s))
#define CP_COMMIT()      asm volatile("cp.async.commit_group;" ::: "memory")
#define CP_WAIT0()       asm volatile("cp.async.wait_group 0;" ::: "memory")

// ===========================================================================
// Transpose NCHW -> [vec, d]; also emit bf16 copy for MMA A tiles.
__global__ void vq_transpose_kernel(const float* __restrict__ z) {
    __shared__ float t[32][33];
    const int p0 = blockIdx.x * 32, d0 = blockIdx.y * 32, b = blockIdx.z;
    const int x = threadIdx.x, y = threadIdx.y;
#pragma unroll
    for (int j = 0; j < 32; j += 8)
        t[y + j][x] = z[b * (DIM * HWD) + (d0 + y + j) * HWD + p0 + x];
    __syncthreads();
#pragma unroll
    for (int j = 0; j < 32; j += 8) {
        const float v = t[x][y + j];
        const size_t o = (size_t)(b * HWD + p0 + y + j) * DIM + d0 + x;
        g_flat[o] = v;
        g_flat_bf16[o] = __float2bfloat16(v);
    }
}

// Codebook norms + bf16 codebook + loss zero. One warp per code.
__global__ void vq_enorm_kernel(const float* __restrict__ emb) {
    const int k = blockIdx.x, lane = threadIdx.x;
    if (k == 0 && lane == 0) g_loss_sum = 0.0;
    const float4* r4 = reinterpret_cast<const float4*>(emb + k * DIM);
    float4 a = r4[lane], b = r4[lane + 32];
    uint32_t* dst = g_emb_bf16 + k * 128;
    __nv_bfloat162 p;
    p = __float22bfloat162_rn(make_float2(a.x, a.y)); dst[lane*2]      = *reinterpret_cast<uint32_t*>(&p);
    p = __float22bfloat162_rn(make_float2(a.z, a.w)); dst[lane*2+1]    = *reinterpret_cast<uint32_t*>(&p);
    p = __float22bfloat162_rn(make_float2(b.x, b.y)); dst[64+lane*2]   = *reinterpret_cast<uint32_t*>(&p);
    p = __float22bfloat162_rn(make_float2(b.z, b.w)); dst[64+lane*2+1] = *reinterpret_cast<uint32_t*>(&p);
    float s = a.x*a.x + a.y*a.y + a.z*a.z + a.w*a.w
            + b.x*b.x + b.y*b.y + b.z*b.z + b.w*b.w;
#pragma unroll
    for (int off = 16; off; off >>= 1) s += __shfl_xor_sync(0xffffffffu, s, off);
    if (lane == 0) g_ee[k] = s;
}

// ===========================================================================
// bf16 mma.sync GEMM (R4-proven addressing) + cp.async double-buffered fills.
// Per CTA: 128 rows x 1024 codes (8 N-tiles), K=256.
// ===========================================================================
#define SM_PITCH 528                      // bytes per padded bf16 row
#define TILE_BYTES (128 * SM_PITCH)       // 67584
#define GEMM_SMEM (3 * TILE_BYTES)        // A + 2x B

__device__ __forceinline__ void mma_bf16(float& c0, float& c1, float& c2, float& c3,
                                         uint32_t a0, uint32_t a1, uint32_t a2, uint32_t a3,
                                         uint32_t b0, uint32_t b1) {
    asm volatile(
        "mma.sync.aligned.m16n8k16.row.col.f32.bf16.bf16.f32 "
        "{%0,%1,%2,%3}, {%4,%5,%6,%7}, {%8,%9}, {%0,%1,%2,%3};"
        : "+f"(c0), "+f"(c1), "+f"(c2), "+f"(c3)
        : "r"(a0), "r"(a1), "r"(a2), "r"(a3), "r"(b0), "r"(b1));
}

// copy a [128 x 512B] bf16 tile into padded smem via cp.async (256 threads)
__device__ __forceinline__ void fill_async(uint32_t tile_s, const char* __restrict__ src, int tid) {
#pragma unroll
    for (int i = tid; i < 4096; i += 256) {
        const int row = i >> 5, ch = (i & 31) << 4;
        CP_ASYNC16(tile_s + row * SM_PITCH + ch, src + row * 512 + ch);
    }
}

__global__ __launch_bounds__(256, 1) void vq_gemm_kernel() {
    extern __shared__ char sm[];
    char* sA  = sm;
    char* sB0 = sm + TILE_BYTES;
    char* sB1 = sm + 2 * TILE_BYTES;
    const uint32_t aA = smem_u32(sA), aB0 = smem_u32(sB0), aB1 = smem_u32(sB1);

    const int tid  = threadIdx.x;
    const int lane = tid & 31;
    const int wid  = tid >> 5;
    const int warp_m = wid & 1;          // 0..1 (64 rows)
    const int warp_n = wid >> 1;         // 0..3 (32 cols)
    const int g   = lane >> 2;
    const int tig = lane & 3;
    const int m0  = blockIdx.x * 128;

    fill_async(aA,  (const char*)g_flat_bf16 + (size_t)m0 * 512, tid);
    fill_async(aB0, (const char*)g_emb_bf16, tid);
    CP_COMMIT();
    CP_WAIT0();
    __syncthreads();

    int aBase[4], bBase[4];
#pragma unroll
    for (int mf = 0; mf < 4; mf++) aBase[mf] = (warp_m * 64 + mf * 16 + g) * SM_PITCH;
#pragma unroll
    for (int nf = 0; nf < 4; nf++) bBase[nf] = (warp_n * 32 + nf * 8 + g) * SM_PITCH;
    const int kb0 = tig * 4;

    for (int t = 0; t < 8; t++) {
        char* sB = (t & 1) ? sB1 : sB0;
        if (t < 7) {
            fill_async(((t + 1) & 1) ? aB1 : aB0,
                       (const char*)g_emb_bf16 + (size_t)(t + 1) * 65536, tid);
            CP_COMMIT();
        }

        float acc[4][4][4];
#pragma unroll
        for (int mf = 0; mf < 4; mf++)
#pragma unroll
            for (int nf = 0; nf < 4; nf++)
#pragma unroll
                for (int c = 0; c < 4; c++) acc[mf][nf][c] = 0.f;

#pragma unroll
        for (int ks = 0; ks < 16; ks++) {
            const int kb = ks * 32 + kb0;
            uint32_t a[4][4], b[4][2];
#pragma unroll
            for (int mf = 0; mf < 4; mf++) {
                const char* p0 = sA + aBase[mf] + kb;
                a[mf][0] = *reinterpret_cast<const uint32_t*>(p0);
                a[mf][1] = *reinterpret_cast<const uint32_t*>(p0 + 8 * SM_PITCH);
                a[mf][2] = *reinterpret_cast<const uint32_t*>(p0 + 16);
                a[mf][3] = *reinterpret_cast<const uint32_t*>(p0 + 8 * SM_PITCH + 16);
            }
#pragma unroll
            for (int nf = 0; nf < 4; nf++) {
                const char* p0 = sB + bBase[nf] + kb;
                b[nf][0] = *reinterpret_cast<const uint32_t*>(p0);
                b[nf][1] = *reinterpret_cast<const uint32_t*>(p0 + 16);
            }
#pragma unroll
            for (int mf = 0; mf < 4; mf++)
#pragma unroll
                for (int nf = 0; nf < 4; nf++)
                    mma_bf16(acc[mf][nf][0], acc[mf][nf][1], acc[mf][nf][2], acc[mf][nf][3],
                             a[mf][0], a[mf][1], a[mf][2], a[mf][3],
                             b[nf][0], b[nf][1]);
        }

        // store bf16 dots for this N-tile (R4-proven layout)
#pragma unroll
        for (int mf = 0; mf < 4; mf++) {
            const int row0 = m0 + warp_m * 64 + mf * 16 + g;
#pragma unroll
            for (int nf = 0; nf < 4; nf++) {
                const int cp = ((t * 128 + warp_n * 32 + nf * 8) >> 1) + tig;
                __nv_bfloat162 lo = __float22bfloat162_rn(
                    make_float2(acc[mf][nf][0], acc[mf][nf][1]));
                __nv_bfloat162 hi = __float22bfloat162_rn(
                    make_float2(acc[mf][nf][2], acc[mf][nf][3]));
                g_dots_u32[(size_t)row0 * (NK/2) + cp]       = *reinterpret_cast<uint32_t*>(&lo);
                g_dots_u32[(size_t)(row0 + 8) * (NK/2) + cp] = *reinterpret_cast<uint32_t*>(&hi);
            }
        }

        if (t < 7) CP_WAIT0();
        __syncthreads();
    }
}

// ===========================================================================
// Scan: warp per row.  Computes xx inline (bit-identical order to the proven
// row_norm2), min approx score -> rigorous-margin candidates -> exact fp32
// rescore (x cached in registers, same fmaf order as proven warp_dot256).
// ===========================================================================
__global__ __launch_bounds__(256) void vq_scan_kernel(const float* __restrict__ emb) {
    const int row  = blockIdx.x * 8 + (threadIdx.x >> 5);
    const int lane = threadIdx.x & 31;
    const uint32_t* drow = g_dots_u32 + (size_t)row * (NK / 2);

    // x row cached in registers
    const float4* x4 = reinterpret_cast<const float4*>(g_flat + (size_t)row * DIM);
    const float4 xa = x4[lane], xb = x4[lane + 32];

    // xx: identical expression + shfl tree as proven row_norm2
    float xx = xa.x*xa.x + xa.y*xa.y + xa.z*xa.z + xa.w*xa.w
             + xb.x*xb.x + xb.y*xb.y + xb.z*xb.z + xb.w*xb.w;
#pragma unroll
    for (int off = 16; off; off >>= 1) xx += __shfl_xor_sync(0xffffffffu, xx, off);

    // rigorous margin: 12*2^-9 * ||x|| * ||e||max + slack   (||e|| < 1/64)
    const float margin = sqrtf(xx) * 0.015625f * (12.0f / 512.0f) + 3e-4f;

    float sv0[16], sv1[16];
    float smin = 3.4e38f;
#pragma unroll
    for (int i = 0; i < 16; i++) {
        uint32_t u = drow[i * 32 + lane];
        __nv_bfloat162 h = *reinterpret_cast<__nv_bfloat162*>(&u);
        float2 d = __bfloat1622float2(h);
        int c0 = i * 64 + lane * 2;
        float s0 = __fadd_rn(__fmaf_rn(-2.0f, d.x, xx), g_ee[c0]);
        float s1 = __fadd_rn(__fmaf_rn(-2.0f, d.y, xx), g_ee[c0 + 1]);
        sv0[i] = s0; sv1[i] = s1;
        smin = fminf(smin, fminf(s0, s1));
    }
#pragma unroll
    for (int off = 16; off; off >>= 1)
        smin = fminf(smin, __shfl_xor_sync(0xffffffffu, smin, off));
    const float thr = smin + margin;

    unsigned long long best = ~0ull;
#pragma unroll 1
    for (int i = 0; i < 16; i++) {
        unsigned mA = __ballot_sync(0xffffffffu, sv0[i] <= thr);
        unsigned mB = __ballot_sync(0xffffffffu, sv1[i] <= thr);
        while (mA | mB) {
            int src, sub;
            if (mA) { src = __ffs(mA) - 1; sub = 0; mA &= mA - 1; }
            else    { src = __ffs(mB) - 1; sub = 1; mB &= mB - 1; }
            const int code = i * 64 + src * 2 + sub;
            const float4* e4 = reinterpret_cast<const float4*>(emb + (size_t)code * DIM);
            const float4 ea = e4[lane], eb = e4[lane + 32];
            float s = xa.x * ea.x;
            s = fmaf(xa.y, ea.y, s); s = fmaf(xa.z, ea.z, s); s = fmaf(xa.w, ea.w, s);
            s = fmaf(xb.x, eb.x, s); s = fmaf(xb.y, eb.y, s);
            s = fmaf(xb.z, eb.z, s); s = fmaf(xb.w, eb.w, s);
#pragma unroll
            for (int off = 16; off; off >>= 1) s += __shfl_xor_sync(0xffffffffu, s, off);
            const float d2 = __fadd_rn(__fmaf_rn(-2.0f, s, xx), g_ee[code]);
            const unsigned long long key =
                ((unsigned long long)__float_as_uint(d2) << 32) | (unsigned)code;
            best = (key < best) ? key : best;
        }
    }
    if (lane == 0) g_win[row] = (int)(best & 0xffffffffu);
}

// ===========================================================================
// Gather + straight-through output + loss (R2/R4-proven, verbatim)
// ===========================================================================
__global__ __launch_bounds__(256) void vq_gather_kernel(const float* __restrict__ emb,
                                                        float* __restrict__ out) {
    __shared__ int   s_idx[128];
    __shared__ float tbuf[32][33];
    __shared__ float wsum[8];

    const int m0 = blockIdx.x * 128;
    const int tid = threadIdx.x;
    if (tid < 128) s_idx[tid] = g_win[m0 + tid];
    __syncthreads();

    const int b_img = m0 >> 10;
    const int hw0   = m0 & (HWD - 1);
    const int dx = tid & 31;
    const int wy = tid >> 5;
    float lsum = 0.f;

    for (int dt = 0; dt < DIM; dt += 32) {
        for (int vt = 0; vt < 128; vt += 32) {
#pragma unroll
            for (int vv = 0; vv < 32; vv += 8) {
                const int v    = vt + vv + wy;
                const int code = s_idx[v];
                const float e  = emb[code * DIM + dt + dx];
                const float x  = g_flat[(size_t)(m0 + v) * DIM + dt + dx];
                const float df = __fadd_rn(e, -x);
                lsum += df * df;
                tbuf[vv + wy][dx] = __fadd_rn(x, df);
            }
            __syncthreads();
#pragma unroll
            for (int dd = 0; dd < 32; dd += 8) {
                const int d = dt + dd + wy;
                out[(b_img * DIM + d) * HWD + hw0 + vt + dx] = tbuf[dx][dd + wy];
            }
            __syncthreads();
        }
    }

#pragma unroll
    for (int off = 16; off; off >>= 1) lsum += __shfl_xor_sync(0xffffffffu, lsum, off);
    if ((tid & 31) == 0) wsum[tid >> 5] = lsum;
    __syncthreads();
    if (tid == 0) {
        float tot = 0.f;
#pragma unroll
        for (int w = 0; w < 8; w++) tot += wsum[w];
        atomicAdd(&g_loss_sum, (double)tot);
    }
}

__global__ void vq_finalize_kernel(float* __restrict__ out) {
    const double mean = g_loss_sum * (1.0 / (double)NELEM);
    const float cb = (float)mean;
    out[NELEM + 0] = cb + 0.25f * cb;
    out[NELEM + 1] = cb;
    out[NELEM + 2] = cb;
}

// ===========================================================================
extern "C" void kernel_launch(void* const* d_in, const int* in_sizes, int n_in,
                              void* d_out, int out_size) {
    const float* z   = (const float*)d_in[0];
    const float* emb = (const float*)d_in[1];
    if (n_in >= 2 && in_sizes[0] == NK * DIM && in_sizes[1] == NELEM) {
        const float* t = z; z = emb; emb = t;
    }
    float* out = (float*)d_out;

    cudaFuncSetAttribute(vq_gemm_kernel,
                         cudaFuncAttributeMaxDynamicSharedMemorySize, GEMM_SMEM);

    vq_transpose_kernel<<<dim3(HWD / 32, DIM / 32, NB), dim3(32, 8)>>>(z);
    vq_enorm_kernel<<<NK, 32>>>(emb);
    vq_gemm_kernel<<<NV / 128, 256, GEMM_SMEM>>>();
    vq_scan_kernel<<<NV / 8, 256>>>(emb);
    vq_gather_kernel<<<NV / 128, 256>>>(emb, out);
    vq_finalize_kernel<<<1, 1>>>(out);
}

// round 7
// speedup vs baseline: 6.8017x; 1.0718x over previous
#include <cuda_runtime.h>
#include <cuda_bf16.h>
#include <cstdint>

// Problem constants
#define NB   32
#define DIM  256
#define HWD  1024
#define NV   (NB*HWD)        // 32768 vectors
#define NK   1024            // codes
#define NELEM (NV*DIM)

// Scratch
__device__ float                   g_flat[NV * DIM];       // z transposed [vec, d] fp32
__device__ __align__(16) __nv_bfloat16 g_flat_bf16[NV * DIM];  // bf16 copy (A tiles)
__device__ __align__(16) uint32_t  g_emb_bf16[NK * 128];   // bf16x2 codebook (B tiles)
__device__ float                   g_ee[NK];               // ||e_k||^2
__device__ uint32_t                g_dots_u32[NV * (NK/2)];// approx dots, bf16x2 packed
__device__ int                     g_win[NV];              // winning code per row
__device__ double                  g_loss_sum;
__device__ unsigned                g_done = 0;             // gather completion counter

// ===========================================================================
__device__ __forceinline__ uint32_t smem_u32(const void* p) {
    uint32_t a;
    asm("{ .reg .u64 t; cvta.to.shared.u64 t, %1; cvt.u32.u64 %0, t; }" : "=r"(a) : "l"(p));
    return a;
}
#define CP_ASYNC16(d, s) asm volatile("cp.async.cg.shared.global [%0], [%1], 16;" :: "r"(d), "l"(s))
#define CP_COMMIT()      asm volatile("cp.async.commit_group;" ::: "memory")
#define CP_WAIT0()       asm volatile("cp.async.wait_group 0;" ::: "memory")
#define LDMX4(r, a) \
    asm volatile("ldmatrix.sync.aligned.m8n8.x4.shared.b16 {%0,%1,%2,%3}, [%4];" \
        : "=r"((r)[0]), "=r"((r)[1]), "=r"((r)[2]), "=r"((r)[3]) : "r"(a))
#define LDMX2(r, a) \
    asm volatile("ldmatrix.sync.aligned.m8n8.x2.shared.b16 {%0,%1}, [%2];" \
        : "=r"((r)[0]), "=r"((r)[1]) : "r"(a))

// ===========================================================================
// Transpose NCHW -> [vec, d]; also emit bf16 copy for MMA A tiles.
__global__ void vq_transpose_kernel(const float* __restrict__ z) {
    __shared__ float t[32][33];
    const int p0 = blockIdx.x * 32, d0 = blockIdx.y * 32, b = blockIdx.z;
    const int x = threadIdx.x, y = threadIdx.y;
#pragma unroll
    for (int j = 0; j < 32; j += 8)
        t[y + j][x] = z[b * (DIM * HWD) + (d0 + y + j) * HWD + p0 + x];
    __syncthreads();
#pragma unroll
    for (int j = 0; j < 32; j += 8) {
        const float v = t[x][y + j];
        const size_t o = (size_t)(b * HWD + p0 + y + j) * DIM + d0 + x;
        g_flat[o] = v;
        g_flat_bf16[o] = __float2bfloat16(v);
    }
}

// Codebook norms + bf16 codebook + loss zero. One warp per code.
__global__ void vq_enorm_kernel(const float* __restrict__ emb) {
    const int k = blockIdx.x, lane = threadIdx.x;
    if (k == 0 && lane == 0) g_loss_sum = 0.0;
    const float4* r4 = reinterpret_cast<const float4*>(emb + k * DIM);
    float4 a = r4[lane], b = r4[lane + 32];
    uint32_t* dst = g_emb_bf16 + k * 128;
    __nv_bfloat162 p;
    p = __float22bfloat162_rn(make_float2(a.x, a.y)); dst[lane*2]      = *reinterpret_cast<uint32_t*>(&p);
    p = __float22bfloat162_rn(make_float2(a.z, a.w)); dst[lane*2+1]    = *reinterpret_cast<uint32_t*>(&p);
    p = __float22bfloat162_rn(make_float2(b.x, b.y)); dst[64+lane*2]   = *reinterpret_cast<uint32_t*>(&p);
    p = __float22bfloat162_rn(make_float2(b.z, b.w)); dst[64+lane*2+1] = *reinterpret_cast<uint32_t*>(&p);
    float s = a.x*a.x + a.y*a.y + a.z*a.z + a.w*a.w
            + b.x*b.x + b.y*b.y + b.z*b.z + b.w*b.w;
#pragma unroll
    for (int off = 16; off; off >>= 1) s += __shfl_xor_sync(0xffffffffu, s, off);
    if (lane == 0) g_ee[k] = s;
}

// ===========================================================================
// bf16 mma.sync GEMM, ldmatrix fragment loads, cp.async double-buffered B.
// Per CTA: 128 rows x 1024 codes (8 N-tiles), K=256.
// ===========================================================================
#define SM_PITCH 528                      // bytes per padded bf16 row
#define TILE_BYTES (128 * SM_PITCH)       // 67584
#define GEMM_SMEM (3 * TILE_BYTES)        // A + 2x B

__device__ __forceinline__ void mma_bf16(float& c0, float& c1, float& c2, float& c3,
                                         uint32_t a0, uint32_t a1, uint32_t a2, uint32_t a3,
                                         uint32_t b0, uint32_t b1) {
    asm volatile(
        "mma.sync.aligned.m16n8k16.row.col.f32.bf16.bf16.f32 "
        "{%0,%1,%2,%3}, {%4,%5,%6,%7}, {%8,%9}, {%0,%1,%2,%3};"
        : "+f"(c0), "+f"(c1), "+f"(c2), "+f"(c3)
        : "r"(a0), "r"(a1), "r"(a2), "r"(a3), "r"(b0), "r"(b1));
}

// copy a [128 x 512B] bf16 tile into padded smem via cp.async (256 threads)
__device__ __forceinline__ void fill_async(uint32_t tile_s, const char* __restrict__ src, int tid) {
#pragma unroll
    for (int i = tid; i < 4096; i += 256) {
        const int row = i >> 5, ch = (i & 31) << 4;
        CP_ASYNC16(tile_s + row * SM_PITCH + ch, src + row * 512 + ch);
    }
}

__global__ __launch_bounds__(256, 1) void vq_gemm_kernel() {
    extern __shared__ char sm[];
    const uint32_t aA  = smem_u32(sm);
    const uint32_t aB0 = aA + TILE_BYTES;
    const uint32_t aB1 = aA + 2 * TILE_BYTES;

    const int tid  = threadIdx.x;
    const int lane = tid & 31;
    const int wid  = tid >> 5;
    const int warp_m = wid & 1;          // 0..1 (64 rows)
    const int warp_n = wid >> 1;         // 0..3 (32 cols)
    const int g   = lane >> 2;
    const int tig = lane & 3;
    const int m0  = blockIdx.x * 128;

    fill_async(aA,  (const char*)g_flat_bf16 + (size_t)m0 * 512, tid);
    fill_async(aB0, (const char*)g_emb_bf16, tid);
    CP_COMMIT();
    CP_WAIT0();
    __syncthreads();

    // ldmatrix per-lane addresses.
    // A x4: lanes 0-7 rows+0..7 k+0 | 8-15 rows+8..15 k+0 | 16-23 rows+0..7 +16B | 24-31 rows+8..15 +16B
    const int l7 = lane & 7, lm8 = (lane >> 3) & 1, lm16 = lane >> 4;
    uint32_t aAddr[4];
#pragma unroll
    for (int mf = 0; mf < 4; mf++)
        aAddr[mf] = aA + (uint32_t)((warp_m * 64 + mf * 16 + l7 + lm8 * 8) * SM_PITCH + lm16 * 16);
    // B x2: lanes 0-7 n-rows+0..7 k+0 | 8-15 same rows +16B (lanes 16-31 ignored)
    uint32_t bRow[4];
#pragma unroll
    for (int nf = 0; nf < 4; nf++)
        bRow[nf] = (uint32_t)((warp_n * 32 + nf * 8 + l7) * SM_PITCH + lm8 * 16);

    for (int t = 0; t < 8; t++) {
        const uint32_t bBase = (t & 1) ? aB1 : aB0;
        if (t < 7) {
            fill_async(((t + 1) & 1) ? aB1 : aB0,
                       (const char*)g_emb_bf16 + (size_t)(t + 1) * 65536, tid);
            CP_COMMIT();
        }

        float acc[4][4][4];
#pragma unroll
        for (int mf = 0; mf < 4; mf++)
#pragma unroll
            for (int nf = 0; nf < 4; nf++)
#pragma unroll
                for (int c = 0; c < 4; c++) acc[mf][nf][c] = 0.f;

#pragma unroll
        for (int ks = 0; ks < 16; ks++) {
            const uint32_t kb = ks * 32;
            uint32_t a[4][4], b[4][2];
#pragma unroll
            for (int mf = 0; mf < 4; mf++) LDMX4(a[mf], aAddr[mf] + kb);
#pragma unroll
            for (int nf = 0; nf < 4; nf++) LDMX2(b[nf], bBase + bRow[nf] + kb);
#pragma unroll
            for (int mf = 0; mf < 4; mf++)
#pragma unroll
                for (int nf = 0; nf < 4; nf++)
                    mma_bf16(acc[mf][nf][0], acc[mf][nf][1], acc[mf][nf][2], acc[mf][nf][3],
                             a[mf][0], a[mf][1], a[mf][2], a[mf][3],
                             b[nf][0], b[nf][1]);
        }

        // store bf16 dots for this N-tile (R4-proven layout)
#pragma unroll
        for (int mf = 0; mf < 4; mf++) {
            const int row0 = m0 + warp_m * 64 + mf * 16 + g;
#pragma unroll
            for (int nf = 0; nf < 4; nf++) {
                const int cp = ((t * 128 + warp_n * 32 + nf * 8) >> 1) + tig;
                __nv_bfloat162 lo = __float22bfloat162_rn(
                    make_float2(acc[mf][nf][0], acc[mf][nf][1]));
                __nv_bfloat162 hi = __float22bfloat162_rn(
                    make_float2(acc[mf][nf][2], acc[mf][nf][3]));
                g_dots_u32[(size_t)row0 * (NK/2) + cp]       = *reinterpret_cast<uint32_t*>(&lo);
                g_dots_u32[(size_t)(row0 + 8) * (NK/2) + cp] = *reinterpret_cast<uint32_t*>(&hi);
            }
        }

        if (t < 7) CP_WAIT0();
        __syncthreads();
    }
}

// ===========================================================================
// Scan, two-pass (no register arrays -> no spills).
// Pass 1: streaming min of approx d2.  Pass 2: re-load (L1-hot), recompute
// identical s, filter by rigorous margin, exact fp32 rescore.
// ===========================================================================
__global__ __launch_bounds__(256) void vq_scan_kernel(const float* __restrict__ emb) {
    const int row  = blockIdx.x * 8 + (threadIdx.x >> 5);
    const int lane = threadIdx.x & 31;
    const uint32_t* drow = g_dots_u32 + (size_t)row * (NK / 2);

    const float4* x4 = reinterpret_cast<const float4*>(g_flat + (size_t)row * DIM);
    const float4 xa = x4[lane], xb = x4[lane + 32];

    // xx: identical expression + shfl tree as proven row_norm2
    float xx = xa.x*xa.x + xa.y*xa.y + xa.z*xa.z + xa.w*xa.w
             + xb.x*xb.x + xb.y*xb.y + xb.z*xb.z + xb.w*xb.w;
#pragma unroll
    for (int off = 16; off; off >>= 1) xx += __shfl_xor_sync(0xffffffffu, xx, off);

    // rigorous margin: 12*2^-9 * ||x|| * ||e||max + slack   (||e|| < 1/64)
    const float margin = sqrtf(xx) * 0.015625f * (12.0f / 512.0f) + 3e-4f;

    // pass 1: streaming min
    float smin = 3.4e38f;
#pragma unroll
    for (int i = 0; i < 16; i++) {
        const uint32_t u = __ldg(drow + i * 32 + lane);
        const __nv_bfloat162 h = *reinterpret_cast<const __nv_bfloat162*>(&u);
        const float2 d = __bfloat1622float2(h);
        const int c0 = i * 64 + lane * 2;
        const float s0 = __fadd_rn(__fmaf_rn(-2.0f, d.x, xx), g_ee[c0]);
        const float s1 = __fadd_rn(__fmaf_rn(-2.0f, d.y, xx), g_ee[c0 + 1]);
        smin = fminf(smin, fminf(s0, s1));
    }
#pragma unroll
    for (int off = 16; off; off >>= 1)
        smin = fminf(smin, __shfl_xor_sync(0xffffffffu, smin, off));
    const float thr = smin + margin;

    // pass 2: recompute (deterministic, identical values), filter, rescore
    unsigned long long best = ~0ull;
#pragma unroll 1
    for (int i = 0; i < 16; i++) {
        const uint32_t u = __ldg(drow + i * 32 + lane);
        const __nv_bfloat162 h = *reinterpret_cast<const __nv_bfloat162*>(&u);
        const float2 d = __bfloat1622float2(h);
        const int c0 = i * 64 + lane * 2;
        const float s0 = __fadd_rn(__fmaf_rn(-2.0f, d.x, xx), g_ee[c0]);
        const float s1 = __fadd_rn(__fmaf_rn(-2.0f, d.y, xx), g_ee[c0 + 1]);
        unsigned mA = __ballot_sync(0xffffffffu, s0 <= thr);
        unsigned mB = __ballot_sync(0xffffffffu, s1 <= thr);
        while (mA | mB) {
            int src, sub;
            if (mA) { src = __ffs(mA) - 1; sub = 0; mA &= mA - 1; }
            else    { src = __ffs(mB) - 1; sub = 1; mB &= mB - 1; }
            const int code = i * 64 + src * 2 + sub;
            const float4* e4 = reinterpret_cast<const float4*>(emb + (size_t)code * DIM);
            const float4 ea = e4[lane], eb = e4[lane + 32];
            float s = xa.x * ea.x;
            s = fmaf(xa.y, ea.y, s); s = fmaf(xa.z, ea.z, s); s = fmaf(xa.w, ea.w, s);
            s = fmaf(xb.x, eb.x, s); s = fmaf(xb.y, eb.y, s);
            s = fmaf(xb.z, eb.z, s); s = fmaf(xb.w, eb.w, s);
#pragma unroll
            for (int off = 16; off; off >>= 1) s += __shfl_xor_sync(0xffffffffu, s, off);
            const float d2 = __fadd_rn(__fmaf_rn(-2.0f, s, xx), g_ee[code]);
            const unsigned long long key =
                ((unsigned long long)__float_as_uint(d2) << 32) | (unsigned)code;
            best = (key < best) ? key : best;
        }
    }
    if (lane == 0) g_win[row] = (int)(best & 0xffffffffu);
}

// ===========================================================================
// Gather + straight-through output + loss + fused finalize (last-block).
// ===========================================================================
__global__ __launch_bounds__(256) void vq_gather_kernel(const float* __restrict__ emb,
                                                        float* __restrict__ out) {
    __shared__ int   s_idx[128];
    __shared__ float tbuf[32][33];
    __shared__ float wsum[8];

    const int m0 = blockIdx.x * 128;
    const int tid = threadIdx.x;
    if (tid < 128) s_idx[tid] = g_win[m0 + tid];
    __syncthreads();

    const int b_img = m0 >> 10;
    const int hw0   = m0 & (HWD - 1);
    const int dx = tid & 31;
    const int wy = tid >> 5;
    float lsum = 0.f;

    for (int dt = 0; dt < DIM; dt += 32) {
        for (int vt = 0; vt < 128; vt += 32) {
#pragma unroll
            for (int vv = 0; vv < 32; vv += 8) {
                const int v    = vt + vv + wy;
                const int code = s_idx[v];
                const float e  = emb[code * DIM + dt + dx];
                const float x  = g_flat[(size_t)(m0 + v) * DIM + dt + dx];
                const float df = __fadd_rn(e, -x);
                lsum += df * df;
                tbuf[vv + wy][dx] = __fadd_rn(x, df);
            }
            __syncthreads();
#pragma unroll
            for (int dd = 0; dd < 32; dd += 8) {
                const int d = dt + dd + wy;
                out[(b_img * DIM + d) * HWD + hw0 + vt + dx] = tbuf[dx][dd + wy];
            }
            __syncthreads();
        }
    }

#pragma unroll
    for (int off = 16; off; off >>= 1) lsum += __shfl_xor_sync(0xffffffffu, lsum, off);
    if ((tid & 31) == 0) wsum[tid >> 5] = lsum;
    __syncthreads();
    if (tid == 0) {
        float tot = 0.f;
#pragma unroll
        for (int w = 0; w < 8; w++) tot += wsum[w];
        atomicAdd(&g_loss_sum, (double)tot);
        __threadfence();
        const unsigned done = atomicAdd(&g_done, 1u);
        if (done == (unsigned)(gridDim.x - 1)) {
            __threadfence();
            const double total = atomicAdd(&g_loss_sum, 0.0);  // ordered read
            const float cb = (float)(total * (1.0 / (double)NELEM));
            out[NELEM + 0] = cb + 0.25f * cb;
            out[NELEM + 1] = cb;
            out[NELEM + 2] = cb;
            g_done = 0;  // reset for next graph replay
        }
    }
}

// ===========================================================================
extern "C" void kernel_launch(void* const* d_in, const int* in_sizes, int n_in,
                              void* d_out, int out_size) {
    const float* z   = (const float*)d_in[0];
    const float* emb = (const float*)d_in[1];
    if (n_in >= 2 && in_sizes[0] == NK * DIM && in_sizes[1] == NELEM) {
        const float* t = z; z = emb; emb = t;
    }
    float* out = (float*)d_out;

    cudaFuncSetAttribute(vq_gemm_kernel,
                         cudaFuncAttributeMaxDynamicSharedMemorySize, GEMM_SMEM);

    vq_transpose_kernel<<<dim3(HWD / 32, DIM / 32, NB), dim3(32, 8)>>>(z);
    vq_enorm_kernel<<<NK, 32>>>(emb);
    vq_gemm_kernel<<<NV / 128, 256, GEMM_SMEM>>>();
    vq_scan_kernel<<<NV / 8, 256>>>(emb);
    vq_gather_kernel<<<NV / 128, 256>>>(emb, out);
}

// round 8
// speedup vs baseline: 7.0003x; 1.0292x over previous
#include <cuda_runtime.h>
#include <cuda_bf16.h>
#include <cstdint>

// Problem constants
#define NB   32
#define DIM  256
#define HWD  1024
#define NV   (NB*HWD)        // 32768 vectors
#define NK   1024            // codes
#define NELEM (NV*DIM)

// Scratch
__device__ float                   g_flat[NV * DIM];       // z transposed [vec, d] fp32
__device__ __align__(16) __nv_bfloat16 g_flat_bf16[NV * DIM];  // bf16 copy (A tiles)
__device__ __align__(16) uint32_t  g_emb_bf16[NK * 128];   // bf16x2 codebook (B tiles)
__device__ float                   g_ee[NK];               // ||e_k||^2
__device__ uint32_t                g_y_u32[NV * (NK/2)];   // y = ee - 2*dot, bf16x2 packed
__device__ int                     g_win[NV];              // winning code per row
__device__ double                  g_loss_sum;
__device__ unsigned                g_done = 0;             // gather completion counter

// ===========================================================================
__device__ __forceinline__ uint32_t smem_u32(const void* p) {
    uint32_t a;
    asm("{ .reg .u64 t; cvta.to.shared.u64 t, %1; cvt.u32.u64 %0, t; }" : "=r"(a) : "l"(p));
    return a;
}
#define CP_ASYNC16(d, s) asm volatile("cp.async.cg.shared.global [%0], [%1], 16;" :: "r"(d), "l"(s))
#define CP_COMMIT()      asm volatile("cp.async.commit_group;" ::: "memory")
#define CP_WAIT0()       asm volatile("cp.async.wait_group 0;" ::: "memory")
#define LDMX4(r, a) \
    asm volatile("ldmatrix.sync.aligned.m8n8.x4.shared.b16 {%0,%1,%2,%3}, [%4];" \
        : "=r"((r)[0]), "=r"((r)[1]), "=r"((r)[2]), "=r"((r)[3]) : "r"(a))
#define LDMX2(r, a) \
    asm volatile("ldmatrix.sync.aligned.m8n8.x2.shared.b16 {%0,%1}, [%2];" \
        : "=r"((r)[0]), "=r"((r)[1]) : "r"(a))

// ===========================================================================
// Transpose NCHW -> [vec, d]; also emit bf16 copy for MMA A tiles.
__global__ void vq_transpose_kernel(const float* __restrict__ z) {
    __shared__ float t[32][33];
    const int p0 = blockIdx.x * 32, d0 = blockIdx.y * 32, b = blockIdx.z;
    const int x = threadIdx.x, y = threadIdx.y;
#pragma unroll
    for (int j = 0; j < 32; j += 8)
        t[y + j][x] = z[b * (DIM * HWD) + (d0 + y + j) * HWD + p0 + x];
    __syncthreads();
#pragma unroll
    for (int j = 0; j < 32; j += 8) {
        const float v = t[x][y + j];
        const size_t o = (size_t)(b * HWD + p0 + y + j) * DIM + d0 + x;
        g_flat[o] = v;
        g_flat_bf16[o] = __float2bfloat16(v);
    }
}

// Codebook norms + bf16 codebook + loss zero. One warp per code.
__global__ void vq_enorm_kernel(const float* __restrict__ emb) {
    const int k = blockIdx.x, lane = threadIdx.x;
    if (k == 0 && lane == 0) g_loss_sum = 0.0;
    const float4* r4 = reinterpret_cast<const float4*>(emb + k * DIM);
    float4 a = r4[lane], b = r4[lane + 32];
    uint32_t* dst = g_emb_bf16 + k * 128;
    __nv_bfloat162 p;
    p = __float22bfloat162_rn(make_float2(a.x, a.y)); dst[lane*2]      = *reinterpret_cast<uint32_t*>(&p);
    p = __float22bfloat162_rn(make_float2(a.z, a.w)); dst[lane*2+1]    = *reinterpret_cast<uint32_t*>(&p);
    p = __float22bfloat162_rn(make_float2(b.x, b.y)); dst[64+lane*2]   = *reinterpret_cast<uint32_t*>(&p);
    p = __float22bfloat162_rn(make_float2(b.z, b.w)); dst[64+lane*2+1] = *reinterpret_cast<uint32_t*>(&p);
    float s = a.x*a.x + a.y*a.y + a.z*a.z + a.w*a.w
            + b.x*b.x + b.y*b.y + b.z*b.z + b.w*b.w;
#pragma unroll
    for (int off = 16; off; off >>= 1) s += __shfl_xor_sync(0xffffffffu, s, off);
    if (lane == 0) g_ee[k] = s;
}

// ===========================================================================
// bf16 mma.sync GEMM, ldmatrix loads, cp.async double-buffered B.
// Epilogue stores y = fl(ee - 2*dot) as bf16x2 (score offset from xx).
// ===========================================================================
#define SM_PITCH 528                      // bytes per padded bf16 row
#define TILE_BYTES (128 * SM_PITCH)       // 67584
#define GEMM_SMEM (3 * TILE_BYTES)        // A + 2x B

__device__ __forceinline__ void mma_bf16(float& c0, float& c1, float& c2, float& c3,
                                         uint32_t a0, uint32_t a1, uint32_t a2, uint32_t a3,
                                         uint32_t b0, uint32_t b1) {
    asm volatile(
        "mma.sync.aligned.m16n8k16.row.col.f32.bf16.bf16.f32 "
        "{%0,%1,%2,%3}, {%4,%5,%6,%7}, {%8,%9}, {%0,%1,%2,%3};"
        : "+f"(c0), "+f"(c1), "+f"(c2), "+f"(c3)
        : "r"(a0), "r"(a1), "r"(a2), "r"(a3), "r"(b0), "r"(b1));
}

// copy a [128 x 512B] bf16 tile into padded smem via cp.async (256 threads)
__device__ __forceinline__ void fill_async(uint32_t tile_s, const char* __restrict__ src, int tid) {
#pragma unroll
    for (int i = tid; i < 4096; i += 256) {
        const int row = i >> 5, ch = (i & 31) << 4;
        CP_ASYNC16(tile_s + row * SM_PITCH + ch, src + row * 512 + ch);
    }
}

__global__ __launch_bounds__(256, 1) void vq_gemm_kernel() {
    extern __shared__ char sm[];
    __shared__ float s_ee[NK];
    const uint32_t aA  = smem_u32(sm);
    const uint32_t aB0 = aA + TILE_BYTES;
    const uint32_t aB1 = aA + 2 * TILE_BYTES;

    const int tid  = threadIdx.x;
    const int lane = tid & 31;
    const int wid  = tid >> 5;
    const int warp_m = wid & 1;          // 0..1 (64 rows)
    const int warp_n = wid >> 1;         // 0..3 (32 cols)
    const int g   = lane >> 2;
    const int tig = lane & 3;
    const int m0  = blockIdx.x * 128;

    fill_async(aA,  (const char*)g_flat_bf16 + (size_t)m0 * 512, tid);
    fill_async(aB0, (const char*)g_emb_bf16, tid);
    CP_COMMIT();
#pragma unroll
    for (int i = tid; i < NK; i += 256) s_ee[i] = g_ee[i];
    CP_WAIT0();
    __syncthreads();

    // ldmatrix per-lane addresses (R7-proven)
    const int l7 = lane & 7, lm8 = (lane >> 3) & 1, lm16 = lane >> 4;
    uint32_t aAddr[4];
#pragma unroll
    for (int mf = 0; mf < 4; mf++)
        aAddr[mf] = aA + (uint32_t)((warp_m * 64 + mf * 16 + l7 + lm8 * 8) * SM_PITCH + lm16 * 16);
    uint32_t bRow[4];
#pragma unroll
    for (int nf = 0; nf < 4; nf++)
        bRow[nf] = (uint32_t)((warp_n * 32 + nf * 8 + l7) * SM_PITCH + lm8 * 16);

    for (int t = 0; t < 8; t++) {
        const uint32_t bBase = (t & 1) ? aB1 : aB0;
        if (t < 7) {
            fill_async(((t + 1) & 1) ? aB1 : aB0,
                       (const char*)g_emb_bf16 + (size_t)(t + 1) * 65536, tid);
            CP_COMMIT();
        }

        float acc[4][4][4];
#pragma unroll
        for (int mf = 0; mf < 4; mf++)
#pragma unroll
            for (int nf = 0; nf < 4; nf++)
#pragma unroll
                for (int c = 0; c < 4; c++) acc[mf][nf][c] = 0.f;

#pragma unroll
        for (int ks = 0; ks < 16; ks++) {
            const uint32_t kb = ks * 32;
            uint32_t a[4][4], b[4][2];
#pragma unroll
            for (int mf = 0; mf < 4; mf++) LDMX4(a[mf], aAddr[mf] + kb);
#pragma unroll
            for (int nf = 0; nf < 4; nf++) LDMX2(b[nf], bBase + bRow[nf] + kb);
#pragma unroll
            for (int mf = 0; mf < 4; mf++)
#pragma unroll
                for (int nf = 0; nf < 4; nf++)
                    mma_bf16(acc[mf][nf][0], acc[mf][nf][1], acc[mf][nf][2], acc[mf][nf][3],
                             a[mf][0], a[mf][1], a[mf][2], a[mf][3],
                             b[nf][0], b[nf][1]);
        }

        // epilogue: y = fl(ee - 2*dot) -> bf16x2 (R4-proven store layout)
#pragma unroll
        for (int mf = 0; mf < 4; mf++) {
            const int row0 = m0 + warp_m * 64 + mf * 16 + g;
#pragma unroll
            for (int nf = 0; nf < 4; nf++) {
                const int c0 = t * 128 + warp_n * 32 + nf * 8 + tig * 2;
                const float e0 = s_ee[c0], e1 = s_ee[c0 + 1];
                const int cp = c0 >> 1;
                __nv_bfloat162 lo = __float22bfloat162_rn(
                    make_float2(__fmaf_rn(-2.f, acc[mf][nf][0], e0),
                                __fmaf_rn(-2.f, acc[mf][nf][1], e1)));
                __nv_bfloat162 hi = __float22bfloat162_rn(
                    make_float2(__fmaf_rn(-2.f, acc[mf][nf][2], e0),
                                __fmaf_rn(-2.f, acc[mf][nf][3], e1)));
                g_y_u32[(size_t)row0 * (NK/2) + cp]       = *reinterpret_cast<uint32_t*>(&lo);
                g_y_u32[(size_t)(row0 + 8) * (NK/2) + cp] = *reinterpret_cast<uint32_t*>(&hi);
            }
        }

        if (t < 7) CP_WAIT0();
        __syncthreads();
    }
}

// ===========================================================================
// Scan: warp per row.  Pass 1: packed bf16 hmin2 stream (exact min).
// Pass 2: filter y <= ymin+margin (y converts exactly to fp32), exact fp32
// rescore with reference rounding + lowest-index tie-break.
// ===========================================================================
__global__ __launch_bounds__(256) void vq_scan_kernel(const float* __restrict__ emb) {
    const int row  = blockIdx.x * 8 + (threadIdx.x >> 5);
    const int lane = threadIdx.x & 31;
    const uint32_t* drow = g_y_u32 + (size_t)row * (NK / 2);

    const float4* x4 = reinterpret_cast<const float4*>(g_flat + (size_t)row * DIM);
    const float4 xa = x4[lane], xb = x4[lane + 32];

    // xx: identical expression + shfl tree as proven row_norm2
    float xx = xa.x*xa.x + xa.y*xa.y + xa.z*xa.z + xa.w*xa.w
             + xb.x*xb.x + xb.y*xb.y + xb.z*xb.z + xb.w*xb.w;
#pragma unroll
    for (int off = 16; off; off >>= 1) xx += __shfl_xor_sync(0xffffffffu, xx, off);

    // rigorous margin: 12*2^-9 * ||x|| * ||e||max + slack   (||e|| < 1/64)
    const float margin = sqrtf(xx) * 0.015625f * (12.0f / 512.0f) + 3e-4f;

    // pass 1: packed bf16 running min (exact)
    const uint32_t infbits = 0x7F807F80u;
    __nv_bfloat162 m2 = *reinterpret_cast<const __nv_bfloat162*>(&infbits);
#pragma unroll
    for (int i = 0; i < 16; i++) {
        const uint32_t u = __ldg(drow + i * 32 + lane);
        m2 = __hmin2(m2, *reinterpret_cast<const __nv_bfloat162*>(&u));
    }
    const float2 mf2 = __bfloat1622float2(m2);
    float ymin = fminf(mf2.x, mf2.y);
#pragma unroll
    for (int off = 16; off; off >>= 1)
        ymin = fminf(ymin, __shfl_xor_sync(0xffffffffu, ymin, off));
    const float thr = ymin + margin;

    // pass 2: filter (L1-hot reload), exact rescore of candidates
    unsigned long long best = ~0ull;
#pragma unroll 1
    for (int i = 0; i < 16; i++) {
        const uint32_t u = __ldg(drow + i * 32 + lane);
        const float2 d = __bfloat1622float2(*reinterpret_cast<const __nv_bfloat162*>(&u));
        unsigned mA = __ballot_sync(0xffffffffu, d.x <= thr);
        unsigned mB = __ballot_sync(0xffffffffu, d.y <= thr);
        while (mA | mB) {
            int src, sub;
            if (mA) { src = __ffs(mA) - 1; sub = 0; mA &= mA - 1; }
            else    { src = __ffs(mB) - 1; sub = 1; mB &= mB - 1; }
            const int code = i * 64 + src * 2 + sub;
            const float4* e4 = reinterpret_cast<const float4*>(emb + (size_t)code * DIM);
            const float4 ea = e4[lane], eb = e4[lane + 32];
            float s = xa.x * ea.x;
            s = fmaf(xa.y, ea.y, s); s = fmaf(xa.z, ea.z, s); s = fmaf(xa.w, ea.w, s);
            s = fmaf(xb.x, eb.x, s); s = fmaf(xb.y, eb.y, s);
            s = fmaf(xb.z, eb.z, s); s = fmaf(xb.w, eb.w, s);
#pragma unroll
            for (int off = 16; off; off >>= 1) s += __shfl_xor_sync(0xffffffffu, s, off);
            const float d2 = __fadd_rn(__fmaf_rn(-2.0f, s, xx), g_ee[code]);
            const unsigned long long key =
                ((unsigned long long)__float_as_uint(d2) << 32) | (unsigned)code;
            best = (key < best) ? key : best;
        }
    }
    if (lane == 0) g_win[row] = (int)(best & 0xffffffffu);
}

// ===========================================================================
// Gather + straight-through output + loss + fused finalize (last-block).
// ===========================================================================
__global__ __launch_bounds__(256) void vq_gather_kernel(const float* __restrict__ emb,
                                                        float* __restrict__ out) {
    __shared__ int   s_idx[128];
    __shared__ float tbuf[32][33];
    __shared__ float wsum[8];

    const int m0 = blockIdx.x * 128;
    const int tid = threadIdx.x;
    if (tid < 128) s_idx[tid] = g_win[m0 + tid];
    __syncthreads();

    const int b_img = m0 >> 10;
    const int hw0   = m0 & (HWD - 1);
    const int dx = tid & 31;
    const int wy = tid >> 5;
    float lsum = 0.f;

    for (int dt = 0; dt < DIM; dt += 32) {
        for (int vt = 0; vt < 128; vt += 32) {
#pragma unroll
            for (int vv = 0; vv < 32; vv += 8) {
                const int v    = vt + vv + wy;
                const int code = s_idx[v];
                const float e  = emb[code * DIM + dt + dx];
                const float x  = g_flat[(size_t)(m0 + v) * DIM + dt + dx];
                const float df = __fadd_rn(e, -x);
                lsum += df * df;
                tbuf[vv + wy][dx] = __fadd_rn(x, df);
            }
            __syncthreads();
#pragma unroll
            for (int dd = 0; dd < 32; dd += 8) {
                const int d = dt + dd + wy;
                out[(b_img * DIM + d) * HWD + hw0 + vt + dx] = tbuf[dx][dd + wy];
            }
            __syncthreads();
        }
    }

#pragma unroll
    for (int off = 16; off; off >>= 1) lsum += __shfl_xor_sync(0xffffffffu, lsum, off);
    if ((tid & 31) == 0) wsum[tid >> 5] = lsum;
    __syncthreads();
    if (tid == 0) {
        float tot = 0.f;
#pragma unroll
        for (int w = 0; w < 8; w++) tot += wsum[w];
        atomicAdd(&g_loss_sum, (double)tot);
        __threadfence();
        const unsigned done = atomicAdd(&g_done, 1u);
        if (done == (unsigned)(gridDim.x - 1)) {
            __threadfence();
            const double total = atomicAdd(&g_loss_sum, 0.0);  // ordered read
            const float cb = (float)(total * (1.0 / (double)NELEM));
            out[NELEM + 0] = cb + 0.25f * cb;
            out[NELEM + 1] = cb;
            out[NELEM + 2] = cb;
            g_done = 0;  // reset for next graph replay
        }
    }
}

// ===========================================================================
extern "C" void kernel_launch(void* const* d_in, const int* in_sizes, int n_in,
                              void* d_out, int out_size) {
    const float* z   = (const float*)d_in[0];
    const float* emb = (const float*)d_in[1];
    if (n_in >= 2 && in_sizes[0] == NK * DIM && in_sizes[1] == NELEM) {
        const float* t = z; z = emb; emb = t;
    }
    float* out = (float*)d_out;

    cudaFuncSetAttribute(vq_gemm_kernel,
                         cudaFuncAttributeMaxDynamicSharedMemorySize, GEMM_SMEM);

    vq_transpose_kernel<<<dim3(HWD / 32, DIM / 32, NB), dim3(32, 8)>>>(z);
    vq_enorm_kernel<<<NK, 32>>>(emb);
    vq_gemm_kernel<<<NV / 128, 256, GEMM_SMEM>>>();
    vq_scan_kernel<<<NV / 8, 256>>>(emb);
    vq_gather_kernel<<<NV / 128, 256>>>(emb, out);
}

// round 9
// speedup vs baseline: 7.2375x; 1.0339x over previous
#include <cuda_runtime.h>
#include <cuda_bf16.h>
#include <cstdint>

// Problem constants
#define NB   32
#define DIM  256
#define HWD  1024
#define NV   (NB*HWD)        // 32768 vectors
#define NK   1024            // codes
#define NELEM (NV*DIM)

// Scratch
__device__ float                   g_flat[NV * DIM];       // z transposed [vec, d] fp32
__device__ __align__(16) __nv_bfloat16 g_flat_bf16[NV * DIM];  // bf16 copy (A tiles)
__device__ __align__(16) uint32_t  g_emb_bf16[NK * 128];   // bf16x2 codebook (B tiles)
__device__ float                   g_ee[NK];               // ||e_k||^2
__device__ __align__(16) uint32_t  g_y_u32[NV * (NK/2)];   // y = ee - 2*dot, bf16x2 packed
__device__ float                   g_ymin[NV];             // per-row min of bf16 y
__device__ int                     g_win[NV];              // winning code per row
__device__ double                  g_loss_sum;
__device__ unsigned                g_done = 0;             // gather completion counter

// ===========================================================================
__device__ __forceinline__ uint32_t smem_u32(const void* p) {
    uint32_t a;
    asm("{ .reg .u64 t; cvta.to.shared.u64 t, %1; cvt.u32.u64 %0, t; }" : "=r"(a) : "l"(p));
    return a;
}
#define CP_ASYNC16(d, s) asm volatile("cp.async.cg.shared.global [%0], [%1], 16;" :: "r"(d), "l"(s))
#define CP_COMMIT()      asm volatile("cp.async.commit_group;" ::: "memory")
#define CP_WAIT0()       asm volatile("cp.async.wait_group 0;" ::: "memory")
#define LDMX4(r, a) \
    asm volatile("ldmatrix.sync.aligned.m8n8.x4.shared.b16 {%0,%1,%2,%3}, [%4];" \
        : "=r"((r)[0]), "=r"((r)[1]), "=r"((r)[2]), "=r"((r)[3]) : "r"(a))
#define LDMX2(r, a) \
    asm volatile("ldmatrix.sync.aligned.m8n8.x2.shared.b16 {%0,%1}, [%2];" \
        : "=r"((r)[0]), "=r"((r)[1]) : "r"(a))

__device__ __forceinline__ __nv_bfloat162 u2b(uint32_t u) {
    return *reinterpret_cast<__nv_bfloat162*>(&u);
}
__device__ __forceinline__ uint32_t b2u(__nv_bfloat162 b) {
    return *reinterpret_cast<uint32_t*>(&b);
}

// ===========================================================================
// Transpose NCHW -> [vec, d]; also emit bf16 copy for MMA A tiles.
__global__ void vq_transpose_kernel(const float* __restrict__ z) {
    __shared__ float t[32][33];
    const int p0 = blockIdx.x * 32, d0 = blockIdx.y * 32, b = blockIdx.z;
    const int x = threadIdx.x, y = threadIdx.y;
#pragma unroll
    for (int j = 0; j < 32; j += 8)
        t[y + j][x] = z[b * (DIM * HWD) + (d0 + y + j) * HWD + p0 + x];
    __syncthreads();
#pragma unroll
    for (int j = 0; j < 32; j += 8) {
        const float v = t[x][y + j];
        const size_t o = (size_t)(b * HWD + p0 + y + j) * DIM + d0 + x;
        g_flat[o] = v;
        g_flat_bf16[o] = __float2bfloat16(v);
    }
}

// Codebook norms + bf16 codebook + loss zero. One warp per code.
__global__ void vq_enorm_kernel(const float* __restrict__ emb) {
    const int k = blockIdx.x, lane = threadIdx.x;
    if (k == 0 && lane == 0) g_loss_sum = 0.0;
    const float4* r4 = reinterpret_cast<const float4*>(emb + k * DIM);
    float4 a = r4[lane], b = r4[lane + 32];
    uint32_t* dst = g_emb_bf16 + k * 128;
    __nv_bfloat162 p;
    p = __float22bfloat162_rn(make_float2(a.x, a.y)); dst[lane*2]      = b2u(p);
    p = __float22bfloat162_rn(make_float2(a.z, a.w)); dst[lane*2+1]    = b2u(p);
    p = __float22bfloat162_rn(make_float2(b.x, b.y)); dst[64+lane*2]   = b2u(p);
    p = __float22bfloat162_rn(make_float2(b.z, b.w)); dst[64+lane*2+1] = b2u(p);
    float s = a.x*a.x + a.y*a.y + a.z*a.z + a.w*a.w
            + b.x*b.x + b.y*b.y + b.z*b.z + b.w*b.w;
#pragma unroll
    for (int off = 16; off; off >>= 1) s += __shfl_xor_sync(0xffffffffu, s, off);
    if (lane == 0) g_ee[k] = s;
}

// ===========================================================================
// bf16 mma.sync GEMM, ldmatrix loads, cp.async double-buffered B.
// Epilogue: stores y = fl(ee - 2*dot) bf16x2 AND keeps per-row running
// hmin2 of the stored bf16 values (register-only; reduced once at the end).
// ===========================================================================
#define SM_PITCH 528                      // bytes per padded bf16 row
#define TILE_BYTES (128 * SM_PITCH)       // 67584
#define GEMM_SMEM (3 * TILE_BYTES)        // A + 2x B

__device__ __forceinline__ void mma_bf16(float& c0, float& c1, float& c2, float& c3,
                                         uint32_t a0, uint32_t a1, uint32_t a2, uint32_t a3,
                                         uint32_t b0, uint32_t b1) {
    asm volatile(
        "mma.sync.aligned.m16n8k16.row.col.f32.bf16.bf16.f32 "
        "{%0,%1,%2,%3}, {%4,%5,%6,%7}, {%8,%9}, {%0,%1,%2,%3};"
        : "+f"(c0), "+f"(c1), "+f"(c2), "+f"(c3)
        : "r"(a0), "r"(a1), "r"(a2), "r"(a3), "r"(b0), "r"(b1));
}

__device__ __forceinline__ void fill_async(uint32_t tile_s, const char* __restrict__ src, int tid) {
#pragma unroll
    for (int i = tid; i < 4096; i += 256) {
        const int row = i >> 5, ch = (i & 31) << 4;
        CP_ASYNC16(tile_s + row * SM_PITCH + ch, src + row * 512 + ch);
    }
}

__global__ __launch_bounds__(256, 1) void vq_gemm_kernel() {
    extern __shared__ char sm[];
    __shared__ float s_ee[NK];
    __shared__ float s_pmin[128][4];
    const uint32_t aA  = smem_u32(sm);
    const uint32_t aB0 = aA + TILE_BYTES;
    const uint32_t aB1 = aA + 2 * TILE_BYTES;

    const int tid  = threadIdx.x;
    const int lane = tid & 31;
    const int wid  = tid >> 5;
    const int warp_m = wid & 1;
    const int warp_n = wid >> 1;
    const int g   = lane >> 2;
    const int tig = lane & 3;
    const int m0  = blockIdx.x * 128;

    fill_async(aA,  (const char*)g_flat_bf16 + (size_t)m0 * 512, tid);
    fill_async(aB0, (const char*)g_emb_bf16, tid);
    CP_COMMIT();
#pragma unroll
    for (int i = tid; i < NK; i += 256) s_ee[i] = g_ee[i];
    CP_WAIT0();
    __syncthreads();

    // ldmatrix per-lane addresses (R7-proven)
    const int l7 = lane & 7, lm8 = (lane >> 3) & 1, lm16 = lane >> 4;
    uint32_t aAddr[4];
#pragma unroll
    for (int mf = 0; mf < 4; mf++)
        aAddr[mf] = aA + (uint32_t)((warp_m * 64 + mf * 16 + l7 + lm8 * 8) * SM_PITCH + lm16 * 16);
    uint32_t bRow[4];
#pragma unroll
    for (int nf = 0; nf < 4; nf++)
        bRow[nf] = (uint32_t)((warp_n * 32 + nf * 8 + l7) * SM_PITCH + lm8 * 16);

    // per-row running bf16 min (row r1 per mf -> mlo, row r2 -> mhi)
    const uint32_t infbits = 0x7F807F80u;
    uint32_t mlo[4], mhi[4];
#pragma unroll
    for (int mf = 0; mf < 4; mf++) { mlo[mf] = infbits; mhi[mf] = infbits; }

    for (int t = 0; t < 8; t++) {
        const uint32_t bBase = (t & 1) ? aB1 : aB0;
        if (t < 7) {
            fill_async(((t + 1) & 1) ? aB1 : aB0,
                       (const char*)g_emb_bf16 + (size_t)(t + 1) * 65536, tid);
            CP_COMMIT();
        }

        float acc[4][4][4];
#pragma unroll
        for (int mf = 0; mf < 4; mf++)
#pragma unroll
            for (int nf = 0; nf < 4; nf++)
#pragma unroll
                for (int c = 0; c < 4; c++) acc[mf][nf][c] = 0.f;

#pragma unroll
        for (int ks = 0; ks < 16; ks++) {
            const uint32_t kb = ks * 32;
            uint32_t a[4][4], b[4][2];
#pragma unroll
            for (int mf = 0; mf < 4; mf++) LDMX4(a[mf], aAddr[mf] + kb);
#pragma unroll
            for (int nf = 0; nf < 4; nf++) LDMX2(b[nf], bBase + bRow[nf] + kb);
#pragma unroll
            for (int mf = 0; mf < 4; mf++)
#pragma unroll
                for (int nf = 0; nf < 4; nf++)
                    mma_bf16(acc[mf][nf][0], acc[mf][nf][1], acc[mf][nf][2], acc[mf][nf][3],
                             a[mf][0], a[mf][1], a[mf][2], a[mf][3],
                             b[nf][0], b[nf][1]);
        }

        // epilogue: y = fl(ee - 2*dot) -> bf16x2; fold into running min
#pragma unroll
        for (int mf = 0; mf < 4; mf++) {
            const int row0 = m0 + warp_m * 64 + mf * 16 + g;
#pragma unroll
            for (int nf = 0; nf < 4; nf++) {
                const int c0 = t * 128 + warp_n * 32 + nf * 8 + tig * 2;
                const float e0 = s_ee[c0], e1 = s_ee[c0 + 1];
                const int cp = c0 >> 1;
                __nv_bfloat162 lo = __float22bfloat162_rn(
                    make_float2(__fmaf_rn(-2.f, acc[mf][nf][0], e0),
                                __fmaf_rn(-2.f, acc[mf][nf][1], e1)));
                __nv_bfloat162 hi = __float22bfloat162_rn(
                    make_float2(__fmaf_rn(-2.f, acc[mf][nf][2], e0),
                                __fmaf_rn(-2.f, acc[mf][nf][3], e1)));
                g_y_u32[(size_t)row0 * (NK/2) + cp]       = b2u(lo);
                g_y_u32[(size_t)(row0 + 8) * (NK/2) + cp] = b2u(hi);
                mlo[mf] = b2u(__hmin2(u2b(mlo[mf]), lo));
                mhi[mf] = b2u(__hmin2(u2b(mhi[mf]), hi));
            }
        }

        if (t < 7) CP_WAIT0();
        __syncthreads();
    }

    // final per-row min: quad shuffle (across tig), then cross-warp smem tree
#pragma unroll
    for (int mf = 0; mf < 4; mf++) {
        uint32_t v = mlo[mf];
        v = b2u(__hmin2(u2b(v), u2b(__shfl_xor_sync(0xffffffffu, v, 1))));
        v = b2u(__hmin2(u2b(v), u2b(__shfl_xor_sync(0xffffffffu, v, 2))));
        uint32_t w = mhi[mf];
        w = b2u(__hmin2(u2b(w), u2b(__shfl_xor_sync(0xffffffffu, w, 1))));
        w = b2u(__hmin2(u2b(w), u2b(__shfl_xor_sync(0xffffffffu, w, 2))));
        if (tig == 0) {
            const float2 f1 = __bfloat1622float2(u2b(v));
            const float2 f2 = __bfloat1622float2(u2b(w));
            s_pmin[warp_m * 64 + mf * 16 + g][warp_n]     = fminf(f1.x, f1.y);
            s_pmin[warp_m * 64 + mf * 16 + g + 8][warp_n] = fminf(f2.x, f2.y);
        }
    }
    __syncthreads();
    if (tid < 128)
        g_ymin[m0 + tid] = fminf(fminf(s_pmin[tid][0], s_pmin[tid][1]),
                                 fminf(s_pmin[tid][2], s_pmin[tid][3]));
}

// ===========================================================================
// Scan: warp per row, SINGLE pass with uint4 loads.
// thr = g_ymin[row] + rigorous margin; filter; exact fp32 rescore
// (reference rounding + lowest-index tie-break).
// ===========================================================================
__global__ __launch_bounds__(256) void vq_scan_kernel(const float* __restrict__ emb) {
    const int row  = blockIdx.x * 8 + (threadIdx.x >> 5);
    const int lane = threadIdx.x & 31;
    const uint4* drow4 = reinterpret_cast<const uint4*>(g_y_u32 + (size_t)row * (NK / 2));

    const float4* x4 = reinterpret_cast<const float4*>(g_flat + (size_t)row * DIM);
    const float4 xa = x4[lane], xb = x4[lane + 32];

    // xx: identical expression + shfl tree as proven row_norm2
    float xx = xa.x*xa.x + xa.y*xa.y + xa.z*xa.z + xa.w*xa.w
             + xb.x*xb.x + xb.y*xb.y + xb.z*xb.z + xb.w*xb.w;
#pragma unroll
    for (int off = 16; off; off >>= 1) xx += __shfl_xor_sync(0xffffffffu, xx, off);

    // rigorous margin: 12*2^-9 * ||x|| * ||e||max + slack   (||e|| < 1/64)
    const float margin = sqrtf(xx) * 0.015625f * (12.0f / 512.0f) + 3e-4f;
    const float thr = g_ymin[row] + margin;

    unsigned long long best = ~0ull;
#pragma unroll 1
    for (int i = 0; i < 4; i++) {
        const uint4 v = __ldg(drow4 + i * 32 + lane);
        uint32_t comp[4] = {v.x, v.y, v.z, v.w};
#pragma unroll
        for (int w = 0; w < 4; w++) {
            const float2 d = __bfloat1622float2(u2b(comp[w]));
            unsigned mA = __ballot_sync(0xffffffffu, d.x <= thr);
            unsigned mB = __ballot_sync(0xffffffffu, d.y <= thr);
            while (mA | mB) {
                int src, sub;
                if (mA) { src = __ffs(mA) - 1; sub = 0; mA &= mA - 1; }
                else    { src = __ffs(mB) - 1; sub = 1; mB &= mB - 1; }
                const int code = (i * 32 + src) * 8 + w * 2 + sub;
                const float4* e4 = reinterpret_cast<const float4*>(emb + (size_t)code * DIM);
                const float4 ea = e4[lane], eb = e4[lane + 32];
                float s = xa.x * ea.x;
                s = fmaf(xa.y, ea.y, s); s = fmaf(xa.z, ea.z, s); s = fmaf(xa.w, ea.w, s);
                s = fmaf(xb.x, eb.x, s); s = fmaf(xb.y, eb.y, s);
                s = fmaf(xb.z, eb.z, s); s = fmaf(xb.w, eb.w, s);
#pragma unroll
                for (int off = 16; off; off >>= 1) s += __shfl_xor_sync(0xffffffffu, s, off);
                const float d2 = __fadd_rn(__fmaf_rn(-2.0f, s, xx), g_ee[code]);
                const unsigned long long key =
                    ((unsigned long long)__float_as_uint(d2) << 32) | (unsigned)code;
                best = (key < best) ? key : best;
            }
        }
    }
    if (lane == 0) g_win[row] = (int)(best & 0xffffffffu);
}

// ===========================================================================
// Gather + straight-through output + loss + fused finalize (last-block).
// ===========================================================================
__global__ __launch_bounds__(256) void vq_gather_kernel(const float* __restrict__ emb,
                                                        float* __restrict__ out) {
    __shared__ int   s_idx[128];
    __shared__ float tbuf[32][33];
    __shared__ float wsum[8];

    const int m0 = blockIdx.x * 128;
    const int tid = threadIdx.x;
    if (tid < 128) s_idx[tid] = g_win[m0 + tid];
    __syncthreads();

    const int b_img = m0 >> 10;
    const int hw0   = m0 & (HWD - 1);
    const int dx = tid & 31;
    const int wy = tid >> 5;
    float lsum = 0.f;

    for (int dt = 0; dt < DIM; dt += 32) {
        for (int vt = 0; vt < 128; vt += 32) {
#pragma unroll
            for (int vv = 0; vv < 32; vv += 8) {
                const int v    = vt + vv + wy;
                const int code = s_idx[v];
                const float e  = emb[code * DIM + dt + dx];
                const float x  = g_flat[(size_t)(m0 + v) * DIM + dt + dx];
                const float df = __fadd_rn(e, -x);
                lsum += df * df;
                tbuf[vv + wy][dx] = __fadd_rn(x, df);
            }
            __syncthreads();
#pragma unroll
            for (int dd = 0; dd < 32; dd += 8) {
                const int d = dt + dd + wy;
                out[(b_img * DIM + d) * HWD + hw0 + vt + dx] = tbuf[dx][dd + wy];
            }
            __syncthreads();
        }
    }

#pragma unroll
    for (int off = 16; off; off >>= 1) lsum += __shfl_xor_sync(0xffffffffu, lsum, off);
    if ((tid & 31) == 0) wsum[tid >> 5] = lsum;
    __syncthreads();
    if (tid == 0) {
        float tot = 0.f;
#pragma unroll
        for (int w = 0; w < 8; w++) tot += wsum[w];
        atomicAdd(&g_loss_sum, (double)tot);
        __threadfence();
        const unsigned done = atomicAdd(&g_done, 1u);
        if (done == (unsigned)(gridDim.x - 1)) {
            __threadfence();
            const double total = atomicAdd(&g_loss_sum, 0.0);  // ordered read
            const float cb = (float)(total * (1.0 / (double)NELEM));
            out[NELEM + 0] = cb + 0.25f * cb;
            out[NELEM + 1] = cb;
            out[NELEM + 2] = cb;
            g_done = 0;  // reset for next graph replay
        }
    }
}

// ===========================================================================
extern "C" void kernel_launch(void* const* d_in, const int* in_sizes, int n_in,
                              void* d_out, int out_size) {
    const float* z   = (const float*)d_in[0];
    const float* emb = (const float*)d_in[1];
    if (n_in >= 2 && in_sizes[0] == NK * DIM && in_sizes[1] == NELEM) {
        const float* t = z; z = emb; emb = t;
    }
    float* out = (float*)d_out;

    cudaFuncSetAttribute(vq_gemm_kernel,
                         cudaFuncAttributeMaxDynamicSharedMemorySize, GEMM_SMEM);

    vq_transpose_kernel<<<dim3(HWD / 32, DIM / 32, NB), dim3(32, 8)>>>(z);
    vq_enorm_kernel<<<NK, 32>>>(emb);
    vq_gemm_kernel<<<NV / 128, 256, GEMM_SMEM>>>();
    vq_scan_kernel<<<NV / 8, 256>>>(emb);
    vq_gather_kernel<<<NV / 128, 256>>>(emb, out);
}